// round 5
// baseline (speedup 1.0000x reference)
#include <cuda_runtime.h>

#define N_NODES 50000
#define N_EDGES 600000
#define DIM 128
#define LN_EPS 1e-5f

// ---- scratch (no allocations allowed) ----
__device__ float g_agg[(size_t)N_NODES * DIM];   // 25.6 MB
__device__ int   g_deg_src[N_NODES];
__device__ int   g_deg_dst[N_NODES];

// ---------------------------------------------------------------------------
// 1) zero agg + degree counters
// ---------------------------------------------------------------------------
__global__ void zero_kernel() {
    int idx = blockIdx.x * blockDim.x + threadIdx.x;
    const int n4 = N_NODES * DIM / 4;           // 1.6M float4
    if (idx < n4) ((float4*)g_agg)[idx] = make_float4(0.f, 0.f, 0.f, 0.f);
    if (idx < N_NODES) { g_deg_src[idx] = 0; g_deg_dst[idx] = 0; }
}

// ---------------------------------------------------------------------------
// 2) degree histogram (avg 12 hits/counter -> low contention)
// ---------------------------------------------------------------------------
__global__ void deg_kernel(const int* __restrict__ src, const int* __restrict__ dst) {
    int e = blockIdx.x * blockDim.x + threadIdx.x;
    if (e < N_EDGES) {
        atomicAdd(&g_deg_src[src[e]], 1);
        atomicAdd(&g_deg_dst[dst[e]], 1);
    }
}

// ---------------------------------------------------------------------------
// 3) edge scatter: agg[dst] += feat[src] * rsqrt(max(out_deg[src],1))
//    one warp per edge, each lane owns 4 floats, vector RED (no return)
// ---------------------------------------------------------------------------
__global__ void scatter_kernel(const float* __restrict__ feat,
                               const int* __restrict__ src,
                               const int* __restrict__ dst) {
    int gid  = blockIdx.x * blockDim.x + threadIdx.x;
    int e    = gid >> 5;
    int lane = gid & 31;
    if (e >= N_EDGES) return;

    const int s = __ldg(&src[e]);
    const int d = __ldg(&dst[e]);
    const float scale = rsqrtf(fmaxf((float)g_deg_src[s], 1.0f));

    float4 v = __ldg((const float4*)(feat + (size_t)s * DIM) + lane);
    v.x *= scale; v.y *= scale; v.z *= scale; v.w *= scale;

    unsigned long long p = (unsigned long long)(g_agg + (size_t)d * DIM + lane * 4);
    asm volatile("red.global.add.v4.f32 [%0], {%1,%2,%3,%4};"
                 :: "l"(p), "f"(v.x), "f"(v.y), "f"(v.z), "f"(v.w)
                 : "memory");
}

// ---------------------------------------------------------------------------
// 4) fused GEMM + bias + residual + LayerNorm + ReLU
//    rst = [agg*in_norm | feat] @ [fc_w; res_w] + in_norm*fc_b
//    out = relu(layernorm(rst))
//    Block: 256 thr, tile M=64 x N=128, K=256 in 8 chunks of 32.
//    Thread computes 8 rows x 4 cols.
// ---------------------------------------------------------------------------
#define BM 64
#define KT 32
#define SA_STRIDE 33   // [BM][33] padded rows (conflict-free stores, bcast reads)

__global__ __launch_bounds__(256, 2) void gemm_ln_kernel(
    const float* __restrict__ feat,
    const float* __restrict__ fc_w,
    const float* __restrict__ fc_b,
    const float* __restrict__ res_w,
    const float* __restrict__ ln_g,
    const float* __restrict__ ln_b,
    float* __restrict__ out)
{
    // sbuf serves as {sA | sW} during the K loop (6208 floats used),
    // then reused as the 64x128 output tile for the LayerNorm phase.
    __shared__ float sbuf[BM * DIM];        // 32 KB
    __shared__ float sInorm[BM];

    float* sA = sbuf;                       // BM * 33 = 2112 floats
    float* sW = sbuf + BM * SA_STRIDE;      // KT * 128 = 4096 floats

    const int tid = threadIdx.x;
    const int tx  = tid & 31;               // output cols tx*4 .. tx*4+3
    const int ty  = tid >> 5;               // output rows ty*8 .. ty*8+7
    const int bm  = blockIdx.x * BM;

    if (tid < BM) {
        int node = bm + tid;
        float dn = (node < N_NODES) ? (float)g_deg_dst[node] : 1.0f;
        sInorm[tid] = rsqrtf(fmaxf(dn, 1.0f));
    }

    float acc[8][4];
#pragma unroll
    for (int i = 0; i < 8; i++)
#pragma unroll
        for (int j = 0; j < 4; j++) acc[i][j] = 0.f;

    for (int kt = 0; kt < 2 * DIM; kt += KT) {
        __syncthreads();    // guards sInorm (first iter) + smem WAR reuse

        // ---- stage W tile [KT][128]: W = [fc_w ; res_w] ----
#pragma unroll
        for (int i = 0; i < 4; i++) {
            int u  = tid + i * 256;          // float4 unit, 1024 total
            int k  = u >> 5;
            int c4 = u & 31;
            int kg = kt + k;
            const float* wrow = (kg < DIM) ? (fc_w + (size_t)kg * DIM)
                                           : (res_w + (size_t)(kg - DIM) * DIM);
            float4 w4 = __ldg((const float4*)wrow + c4);
            *((float4*)(sW + k * DIM) + c4) = w4;
        }

        // ---- stage A tile [BM][KT] (row-major, padded stride 33) ----
#pragma unroll
        for (int i = 0; i < 2; i++) {
            int u  = tid + i * 256;          // 512 float4 units
            int m  = u >> 3;
            int kq = u & 7;
            int node  = bm + m;
            int nodec = (node < N_NODES) ? node : (N_NODES - 1);
            int kg = kt + kq * 4;
            float4 a4;
            if (kg < DIM) {
                a4 = __ldg((const float4*)(g_agg + (size_t)nodec * DIM + kg));
                float sc = sInorm[m];
                a4.x *= sc; a4.y *= sc; a4.z *= sc; a4.w *= sc;
            } else {
                a4 = __ldg((const float4*)(feat + (size_t)nodec * DIM + (kg - DIM)));
            }
            float* arow = sA + m * SA_STRIDE + kq * 4;
            arow[0] = a4.x; arow[1] = a4.y; arow[2] = a4.z; arow[3] = a4.w;
        }

        __syncthreads();

        // ---- compute: 32 FFMA x2 per k per thread ----
#pragma unroll
        for (int k = 0; k < KT; k++) {
            float4 b4 = *((float4*)(sW + k * DIM) + tx);
            float a[8];
#pragma unroll
            for (int i = 0; i < 8; i++)
                a[i] = sA[(ty * 8 + i) * SA_STRIDE + k];   // warp-broadcast
#pragma unroll
            for (int i = 0; i < 8; i++) {
                acc[i][0] = fmaf(a[i], b4.x, acc[i][0]);
                acc[i][1] = fmaf(a[i], b4.y, acc[i][1]);
                acc[i][2] = fmaf(a[i], b4.z, acc[i][2]);
                acc[i][3] = fmaf(a[i], b4.w, acc[i][3]);
            }
        }
    }

    // ---- epilogue: + in_norm*fc_b, stage tile to smem ----
    float4 bias4 = __ldg((const float4*)fc_b + tx);
    __syncthreads();    // done reading sA/sW; sbuf becomes output tile
#pragma unroll
    for (int i = 0; i < 8; i++) {
        int m = ty * 8 + i;
        float inn = sInorm[m];
        float4 v;
        v.x = acc[i][0] + inn * bias4.x;
        v.y = acc[i][1] + inn * bias4.y;
        v.z = acc[i][2] + inn * bias4.z;
        v.w = acc[i][3] + inn * bias4.w;
        *((float4*)(sbuf + m * DIM) + tx) = v;
    }
    __syncthreads();

    // ---- LayerNorm + ReLU: warp `ty` handles rows ty*8..ty*8+7 ----
    const int lane = tx;
#pragma unroll
    for (int r = 0; r < 8; r++) {
        int row = ty * 8 + r;
        float v0 = sbuf[row * DIM + lane];
        float v1 = sbuf[row * DIM + lane + 32];
        float v2 = sbuf[row * DIM + lane + 64];
        float v3 = sbuf[row * DIM + lane + 96];
        float s = v0 + v1 + v2 + v3;
        float q = v0 * v0 + v1 * v1 + v2 * v2 + v3 * v3;
#pragma unroll
        for (int off = 16; off > 0; off >>= 1) {
            s += __shfl_xor_sync(0xffffffffu, s, off);
            q += __shfl_xor_sync(0xffffffffu, q, off);
        }
        float mu   = s * (1.0f / DIM);
        float var  = q * (1.0f / DIM) - mu * mu;
        float rstd = rsqrtf(var + LN_EPS);

        int node = bm + row;
        if (node < N_NODES) {
            float* orow = out + (size_t)node * DIM;
            float g0 = __ldg(&ln_g[lane]),      b0 = __ldg(&ln_b[lane]);
            float g1 = __ldg(&ln_g[lane + 32]), b1 = __ldg(&ln_b[lane + 32]);
            float g2 = __ldg(&ln_g[lane + 64]), b2 = __ldg(&ln_b[lane + 64]);
            float g3 = __ldg(&ln_g[lane + 96]), b3 = __ldg(&ln_b[lane + 96]);
            orow[lane]      = fmaxf(0.f, (v0 - mu) * rstd * g0 + b0);
            orow[lane + 32] = fmaxf(0.f, (v1 - mu) * rstd * g1 + b1);
            orow[lane + 64] = fmaxf(0.f, (v2 - mu) * rstd * g2 + b2);
            orow[lane + 96] = fmaxf(0.f, (v3 - mu) * rstd * g3 + b3);
        }
    }
}

// ---------------------------------------------------------------------------
extern "C" void kernel_launch(void* const* d_in, const int* in_sizes, int n_in,
                              void* d_out, int out_size) {
    const float* feat  = (const float*)d_in[0];
    const int*   src   = (const int*)d_in[1];
    const int*   dst   = (const int*)d_in[2];
    const float* fc_w  = (const float*)d_in[3];
    const float* fc_b  = (const float*)d_in[4];
    const float* res_w = (const float*)d_in[5];
    const float* ln_g  = (const float*)d_in[6];
    const float* ln_b  = (const float*)d_in[7];
    float* out = (float*)d_out;

    (void)in_sizes; (void)n_in; (void)out_size;

    zero_kernel<<<(N_NODES * DIM / 4 + 255) / 256, 256>>>();
    deg_kernel<<<(N_EDGES + 255) / 256, 256>>>(src, dst);
    scatter_kernel<<<(N_EDGES * 32) / 256, 256>>>(feat, src, dst);
    gemm_ln_kernel<<<(N_NODES + BM - 1) / BM, 256>>>(feat, fc_w, fc_b, res_w,
                                                     ln_g, ln_b, out);
}